// round 4
// baseline (speedup 1.0000x reference)
#include <cuda_runtime.h>
#include <cuda_bf16.h>
#include <cstdint>

// Problem constants
#define NB 2        // B
#define LL 16       // L
#define NN 10000    // N
#define FIN 8
#define HH 64       // H
#define PP 12       // P
#define EE 80000    // E
// Only l = 14,15 feed out[:, :, -1]. Slot s = b*2 + (l-14); row = [n][s][64].
#define SLOTS 4
#define ROWF (SLOTS * HH)   // 256 floats per node row
#define CAP 128             // per-node edge bucket capacity (max deg ~30)

// K2 geometry: 16 warps/block, 3 nodes/warp (6 (node,b) pairs), grid 209.
#define K2_WARPS 16
#define K2_THREADS (K2_WARPS * 32)
#define NPW 3
#define NODES_PER_BLOCK (K2_WARPS * NPW)          // 48
#define K2_GRID ((NN + NODES_PER_BLOCK - 1) / NODES_PER_BLOCK)  // 209

// Scratch
__device__ __align__(16) float g_h[(size_t)NN * ROWF];
__device__ int g_cnt[NN];                                // zero-init; K2 self-cleans
__device__ __align__(8) int2 g_edge[(size_t)NN * CAP];   // {col, val_bits}

// ---------------------------------------------------------------------------
// K1: input projection (one warp per (n,s) row, l in {14,15}) + edge binning.
// ---------------------------------------------------------------------------
__global__ void k_proj_bin(const float* __restrict__ x,
                           const float* __restrict__ W_in,
                           const float* __restrict__ b_in,
                           const int* __restrict__ row,
                           const int* __restrict__ col,
                           const float* __restrict__ vals) {
    __shared__ float sW[FIN * HH];
    __shared__ float sb[HH];
    int tid = threadIdx.x;
    int gid = blockIdx.x * blockDim.x + tid;

    if (gid < EE) {
        int r = __ldg(row + gid);
        int rank = atomicAdd(&g_cnt[r], 1);
        if (rank < CAP)
            g_edge[(size_t)r * CAP + rank] =
                make_int2(__ldg(col + gid), __float_as_int(__ldg(vals + gid)));
    }

    for (int i = tid; i < FIN * HH; i += blockDim.x) sW[i] = W_in[i];
    if (tid < HH) sb[tid] = b_in[tid];
    __syncthreads();

    int warp = blockIdx.x * 8 + (tid >> 5);   // exactly 40000
    int lane = tid & 31;
    int n = warp >> 2;
    int s = warp & 3;
    int b = s >> 1;
    int l = 14 + (s & 1);

    const float4* xr = reinterpret_cast<const float4*>(
        x + (((size_t)b * LL + l) * NN + n) * FIN);
    float4 x0 = __ldg(xr);
    float4 x1 = __ldg(xr + 1);
    float xv[8] = {x0.x, x0.y, x0.z, x0.w, x1.x, x1.y, x1.z, x1.w};

    float* hrow = g_h + (size_t)warp * HH;    // warp == n*4+s
    #pragma unroll
    for (int rep = 0; rep < 2; rep++) {
        int hh = lane + rep * 32;
        float acc = sb[hh];
        #pragma unroll
        for (int f = 0; f < 8; f++) acc = fmaf(xv[f], sW[f * HH + hh], acc);
        hrow[hh] = fmaxf(acc, 0.0f);
    }
}

// ---------------------------------------------------------------------------
// K2: per warp, 3 nodes: gather (register accum, prefetched edges), relu ->
// smem u (float4-interleaved), z = relu(Wt*u + b_tcn) for 6 pairs with
// float4-packed weights, y = z @ W_out + b_out.
// Dynamic smem layout (83 KB):
//   sWt4  [32][64] float4 : {w0[2ip], w1[2ip], w0[2ip+1], w1[2ip+1]} per o
//   su4   [16][6][32] float4 : per (warp,pair): {u0[2ip],u1[2ip],u0[2ip+1],u1[2ip+1]}
//                              (reused as z storage after the z-loop)
//   sWoT  [12][64] float  : W_out transposed, float4-readable
//   sbt[64], sbo[12]
// ---------------------------------------------------------------------------
#define SM_WT   0
#define SM_SU   (SM_WT + 32 * 64 * 16)            // 32768
#define SM_WO   (SM_SU + K2_WARPS * NPW * 2 * 32 * 16)  // +49152 = 81920
#define SM_BT   (SM_WO + PP * 64 * 4)             // +3072  = 84992
#define SM_BO   (SM_BT + 64 * 4)                  // +256   = 85248
#define SM_TOT  (SM_BO + 64)                      //        = 85312

__global__ void __launch_bounds__(K2_THREADS, 2)
k_gather_final(const float* __restrict__ W_tcn,
               const float* __restrict__ b_tcn,
               const float* __restrict__ W_out,
               const float* __restrict__ b_out,
               float* __restrict__ out) {
    extern __shared__ char dsm[];
    float4 (*sWt4)[64] = reinterpret_cast<float4(*)[64]>(dsm + SM_WT);
    float4 (*su4)[NPW * 2][32] =
        reinterpret_cast<float4(*)[NPW * 2][32]>(dsm + SM_SU);
    float*  sWoT = reinterpret_cast<float*>(dsm + SM_WO);   // [p][o] p*64+o
    float*  sbt  = reinterpret_cast<float*>(dsm + SM_BT);
    float*  sbo  = reinterpret_cast<float*>(dsm + SM_BO);

    int tid = threadIdx.x;
    for (int idx = tid; idx < 32 * 64; idx += K2_THREADS) {
        int ip = idx >> 6, o = idx & 63;
        const float* wb = W_tcn + o * 192 + ip * 6;   // i = 2ip
        sWt4[ip][o] = make_float4(wb[0], wb[1], wb[3], wb[4]);
    }
    for (int idx = tid; idx < PP * 64; idx += K2_THREADS) {
        int p = idx >> 6, o = idx & 63;
        sWoT[p * 64 + o] = W_out[o * PP + p];
    }
    if (tid < 64) sbt[tid] = b_tcn[tid];
    if (tid < PP) sbo[tid] = b_out[tid];
    __syncthreads();

    int w = tid >> 5, lane = tid & 31;
    int nBase = (blockIdx.x * K2_WARPS + w) * NPW;

    // ---- gather: 3 interleaved streams with edge prefetch ----
    float4 a[NPW][2];
    #pragma unroll
    for (int m = 0; m < NPW; m++) {
        a[m][0] = make_float4(0.f, 0.f, 0.f, 0.f);
        a[m][1] = make_float4(0.f, 0.f, 0.f, 0.f);
    }
    int deg[NPW];
    const int2* ep[NPW];
    int dmax = 0;
    #pragma unroll
    for (int m = 0; m < NPW; m++) {
        int n = nBase + m;
        deg[m] = (n < NN) ? g_cnt[n] : 0;
        if (deg[m] > CAP) deg[m] = CAP;
        ep[m] = g_edge + (size_t)n * CAP;
        dmax = max(dmax, deg[m]);
    }
    int2 enext[NPW];
    #pragma unroll
    for (int m = 0; m < NPW; m++)
        enext[m] = (deg[m] > 0) ? __ldg(ep[m]) : make_int2(0, 0);

    for (int k = 0; k < dmax; k++) {
        int2 e[NPW];
        #pragma unroll
        for (int m = 0; m < NPW; m++) {
            e[m] = enext[m];
            if (k + 1 < deg[m]) enext[m] = __ldg(ep[m] + k + 1);
        }
        #pragma unroll
        for (int m = 0; m < NPW; m++) {
            if (k < deg[m]) {
                float v = __int_as_float(e[m].y);
                const float4* hp = reinterpret_cast<const float4*>(
                    g_h + (size_t)e[m].x * ROWF);
                float4 h0 = __ldg(hp + lane);
                float4 h1 = __ldg(hp + lane + 32);
                a[m][0].x = fmaf(h0.x, v, a[m][0].x);
                a[m][0].y = fmaf(h0.y, v, a[m][0].y);
                a[m][0].z = fmaf(h0.z, v, a[m][0].z);
                a[m][0].w = fmaf(h0.w, v, a[m][0].w);
                a[m][1].x = fmaf(h1.x, v, a[m][1].x);
                a[m][1].y = fmaf(h1.y, v, a[m][1].y);
                a[m][1].z = fmaf(h1.z, v, a[m][1].z);
                a[m][1].w = fmaf(h1.w, v, a[m][1].w);
            }
        }
    }
    if (lane < NPW && nBase + lane < NN) g_cnt[nBase + lane] = 0; // self-clean

    // ---- scatter relu(u) to interleaved su4 ----
    // a[m][hb] holds row floats f = hb*128 + lane*4 + j; slot = (f/64)&1 -> tap,
    // h = f&63. su4 float layout per pair: (h>>1)*4 + (h&1)*2 + tap.
    #pragma unroll
    for (int m = 0; m < NPW; m++) {
        #pragma unroll
        for (int hb = 0; hb < 2; hb++) {           // hb == b index
            float* dst = reinterpret_cast<float*>(&su4[w][m * 2 + hb][0]);
            float vv[4] = {a[m][hb].x, a[m][hb].y, a[m][hb].z, a[m][hb].w};
            #pragma unroll
            for (int j = 0; j < 4; j++) {
                int f = lane * 4 + j;
                int tap = f >> 6;
                int h = f & 63;
                dst[(h >> 1) * 4 + (h & 1) * 2 + tap] = fmaxf(vv[j], 0.0f);
            }
        }
    }
    __syncwarp();

    // ---- z-stage: 6 pairs, float4-packed weights ----
    float z0[NPW * 2], z1[NPW * 2];
    #pragma unroll
    for (int pp = 0; pp < NPW * 2; pp++) {
        z0[pp] = sbt[lane];
        z1[pp] = sbt[lane + 32];
    }
    #pragma unroll 4
    for (int ip = 0; ip < 32; ip++) {
        float4 wA = sWt4[ip][lane];
        float4 wB = sWt4[ip][lane + 32];
        #pragma unroll
        for (int pp = 0; pp < NPW * 2; pp++) {
            float4 u = su4[w][pp][ip];
            z0[pp] = fmaf(wA.x, u.x, fmaf(wA.y, u.y,
                     fmaf(wA.z, u.z, fmaf(wA.w, u.w, z0[pp]))));
            z1[pp] = fmaf(wB.x, u.x, fmaf(wB.y, u.y,
                     fmaf(wB.z, u.z, fmaf(wB.w, u.w, z1[pp]))));
        }
    }
    __syncwarp();
    // reuse su4[w][pp][0..15] as z storage: float index o
    #pragma unroll
    for (int pp = 0; pp < NPW * 2; pp++) {
        float* zf = reinterpret_cast<float*>(&su4[w][pp][0]);
        zf[lane]      = fmaxf(z0[pp], 0.0f);
        zf[lane + 32] = fmaxf(z1[pp], 0.0f);
    }
    __syncwarp();

    // ---- y-stage: 72 outputs (6 pairs x 12) over 3 lane-rounds ----
    #pragma unroll
    for (int r = 0; r < 3; r++) {
        int q = lane + r * 32;
        if (q < NPW * 2 * PP) {
            int pp = q / PP;
            int p  = q - pp * PP;
            float y = sbo[p];
            const float4* z4 = &su4[w][pp][0];
            const float4* w4 = reinterpret_cast<const float4*>(sWoT + p * 64);
            #pragma unroll 4
            for (int oc = 0; oc < 16; oc++) {
                float4 zz = z4[oc];
                float4 ww = w4[oc];
                y = fmaf(zz.x, ww.x, fmaf(zz.y, ww.y,
                    fmaf(zz.z, ww.z, fmaf(zz.w, ww.w, y))));
            }
            int node = nBase + (pp >> 1);
            int b = pp & 1;
            if (node < NN)
                out[((size_t)b * PP + p) * NN + node] = y;
        }
    }
}

// ---------------------------------------------------------------------------
extern "C" void kernel_launch(void* const* d_in, const int* in_sizes, int n_in,
                              void* d_out, int out_size) {
    const float* x     = (const float*)d_in[0];
    const int*   row   = (const int*)  d_in[1];
    const int*   col   = (const int*)  d_in[2];
    const float* vals  = (const float*)d_in[3];
    const float* W_in  = (const float*)d_in[4];
    const float* b_in  = (const float*)d_in[5];
    const float* W_tcn = (const float*)d_in[6];
    const float* b_tcn = (const float*)d_in[7];
    const float* W_out = (const float*)d_in[8];
    const float* b_out = (const float*)d_in[9];
    float* out = (float*)d_out;

    static bool attr_set = false;
    if (!attr_set) {
        cudaFuncSetAttribute(k_gather_final,
                             cudaFuncAttributeMaxDynamicSharedMemorySize, SM_TOT);
        attr_set = true;
    }

    k_proj_bin<<<5000, 256>>>(x, W_in, b_in, row, col, vals);
    k_gather_final<<<K2_GRID, K2_THREADS, SM_TOT>>>(W_tcn, b_tcn, W_out, b_out, out);
}

// round 5
// speedup vs baseline: 1.3400x; 1.3400x over previous
#include <cuda_runtime.h>
#include <cuda_bf16.h>
#include <cstdint>

// Problem constants
#define NB 2        // B
#define LL 16       // L
#define NN 10000    // N
#define FIN 8
#define HH 64       // H
#define PP 12       // P
#define EE 80000    // E
// Only l = 14,15 feed out[:, :, -1]. Slot s = b*2 + (l-14); row = [n][s][64].
#define SLOTS 4
#define ROWF (SLOTS * HH)   // 256 floats per node row
#define CAP 128             // per-node edge bucket capacity (max deg ~35)

// Scratch
__device__ __align__(16) float g_h[(size_t)NN * ROWF];
__device__ __align__(16) float g_agg[(size_t)NN * ROWF];   // relu'd aggregate
__device__ int g_cnt[NN];                                  // zero-init; K2 cleans
__device__ __align__(8) int2 g_edge[(size_t)NN * CAP];     // {col, val_bits}

// ---------------------------------------------------------------------------
// K1: one warp per node: h[n,s,:] = relu(x[b,l,n,:]@W_in + b_in), s=0..3
//     (l in {14,15}); plus edge binning on the first EE threads.
// Grid 1250 x 256 = 10000 warps exact; 320000 threads >= EE.
// ---------------------------------------------------------------------------
__global__ void k_proj_bin(const float* __restrict__ x,
                           const float* __restrict__ W_in,
                           const float* __restrict__ b_in,
                           const int* __restrict__ row,
                           const int* __restrict__ col,
                           const float* __restrict__ vals) {
    __shared__ float sW[FIN * HH];
    __shared__ float sb[HH];
    int tid = threadIdx.x;
    int gid = blockIdx.x * blockDim.x + tid;

    if (gid < EE) {
        int r = __ldg(row + gid);
        int rank = atomicAdd(&g_cnt[r], 1);
        if (rank < CAP)
            g_edge[(size_t)r * CAP + rank] =
                make_int2(__ldg(col + gid), __float_as_int(__ldg(vals + gid)));
    }

    for (int i = tid; i < FIN * HH; i += blockDim.x) sW[i] = W_in[i];
    if (tid < HH) sb[tid] = b_in[tid];
    __syncthreads();

    int n = blockIdx.x * 8 + (tid >> 5);   // exactly 10000
    int lane = tid & 31;

    #pragma unroll
    for (int s = 0; s < SLOTS; s++) {
        int b = s >> 1;
        int l = 14 + (s & 1);
        const float4* xr = reinterpret_cast<const float4*>(
            x + (((size_t)b * LL + l) * NN + n) * FIN);
        float4 x0 = __ldg(xr);       // warp-broadcast 32B row
        float4 x1 = __ldg(xr + 1);
        float xv[8] = {x0.x, x0.y, x0.z, x0.w, x1.x, x1.y, x1.z, x1.w};

        float* hrow = g_h + ((size_t)n * SLOTS + s) * HH;
        #pragma unroll
        for (int rep = 0; rep < 2; rep++) {
            int hh = lane + rep * 32;
            float acc = sb[hh];
            #pragma unroll
            for (int f = 0; f < 8; f++) acc = fmaf(xv[f], sW[f * HH + hh], acc);
            hrow[hh] = fmaxf(acc, 0.0f);
        }
    }
}

// ---------------------------------------------------------------------------
// K2: gather, one warp per node. Edge list loaded lane-parallel (one LDG.64
// for up to 32 edges), shfl-broadcast; edge loop unrolled x2 with dual
// accumulators -> 4 independent LDG.128 in flight. relu applied at the write.
// ---------------------------------------------------------------------------
__global__ void k_gather() {
    int n = blockIdx.x * 8 + (threadIdx.x >> 5);   // exactly 10000 warps
    int lane = threadIdx.x & 31;

    int deg = g_cnt[n];
    if (deg > CAP) deg = CAP;
    if (lane == 0) g_cnt[n] = 0;                   // self-clean for next call
    const int2* ep = g_edge + (size_t)n * CAP;

    float4 a0 = make_float4(0.f, 0.f, 0.f, 0.f);
    float4 a1 = make_float4(0.f, 0.f, 0.f, 0.f);
    float4 c0 = make_float4(0.f, 0.f, 0.f, 0.f);
    float4 c1 = make_float4(0.f, 0.f, 0.f, 0.f);

    for (int base = 0; base < deg; base += 32) {
        int idx = base + lane;
        int2 e = (idx < deg) ? __ldg(ep + idx) : make_int2(0, 0);
        int cnt = min(32, deg - base);
        int k = 0;
        for (; k + 1 < cnt; k += 2) {
            int   cA = __shfl_sync(0xffffffffu, e.x, k);
            float vA = __int_as_float(__shfl_sync(0xffffffffu, e.y, k));
            int   cB = __shfl_sync(0xffffffffu, e.x, k + 1);
            float vB = __int_as_float(__shfl_sync(0xffffffffu, e.y, k + 1));
            const float4* hpA = reinterpret_cast<const float4*>(g_h + (size_t)cA * ROWF);
            const float4* hpB = reinterpret_cast<const float4*>(g_h + (size_t)cB * ROWF);
            float4 pA0 = __ldg(hpA + lane);
            float4 pA1 = __ldg(hpA + lane + 32);
            float4 pB0 = __ldg(hpB + lane);
            float4 pB1 = __ldg(hpB + lane + 32);
            a0.x = fmaf(pA0.x, vA, a0.x); a0.y = fmaf(pA0.y, vA, a0.y);
            a0.z = fmaf(pA0.z, vA, a0.z); a0.w = fmaf(pA0.w, vA, a0.w);
            a1.x = fmaf(pA1.x, vA, a1.x); a1.y = fmaf(pA1.y, vA, a1.y);
            a1.z = fmaf(pA1.z, vA, a1.z); a1.w = fmaf(pA1.w, vA, a1.w);
            c0.x = fmaf(pB0.x, vB, c0.x); c0.y = fmaf(pB0.y, vB, c0.y);
            c0.z = fmaf(pB0.z, vB, c0.z); c0.w = fmaf(pB0.w, vB, c0.w);
            c1.x = fmaf(pB1.x, vB, c1.x); c1.y = fmaf(pB1.y, vB, c1.y);
            c1.z = fmaf(pB1.z, vB, c1.z); c1.w = fmaf(pB1.w, vB, c1.w);
        }
        if (k < cnt) {
            int   cA = __shfl_sync(0xffffffffu, e.x, k);
            float vA = __int_as_float(__shfl_sync(0xffffffffu, e.y, k));
            const float4* hpA = reinterpret_cast<const float4*>(g_h + (size_t)cA * ROWF);
            float4 pA0 = __ldg(hpA + lane);
            float4 pA1 = __ldg(hpA + lane + 32);
            a0.x = fmaf(pA0.x, vA, a0.x); a0.y = fmaf(pA0.y, vA, a0.y);
            a0.z = fmaf(pA0.z, vA, a0.z); a0.w = fmaf(pA0.w, vA, a0.w);
            a1.x = fmaf(pA1.x, vA, a1.x); a1.y = fmaf(pA1.y, vA, a1.y);
            a1.z = fmaf(pA1.z, vA, a1.z); a1.w = fmaf(pA1.w, vA, a1.w);
        }
    }

    float4* ap = reinterpret_cast<float4*>(g_agg + (size_t)n * ROWF);
    ap[lane] = make_float4(fmaxf(a0.x + c0.x, 0.f), fmaxf(a0.y + c0.y, 0.f),
                           fmaxf(a0.z + c0.z, 0.f), fmaxf(a0.w + c0.w, 0.f));
    ap[lane + 32] = make_float4(fmaxf(a1.x + c1.x, 0.f), fmaxf(a1.y + c1.y, 0.f),
                                fmaxf(a1.z + c1.z, 0.f), fmaxf(a1.w + c1.w, 0.f));
}

// ---------------------------------------------------------------------------
// K3: final stage, 4 nodes (8 (node,b) pairs) per warp, 8 warps/block.
//   u from g_agg (already relu'd), z = relu(Wt0 u14 + Wt1 u15 + b_tcn),
//   y = z @ W_out + b_out, out[b,p,n] = y[p].
// Dynamic smem:
//   sWt4 [32][64] float4 {w0[2ip], w1[2ip], w0[2ip+1], w1[2ip+1]}
//   su4  [8][8][32] float4 per (warp,pair): {u0[2ip],u1[2ip],u0[2ip+1],u1[2ip+1]}
//        (reused as z after z-loop)
//   sWoT [12][64] float; sbt[64]; sbo[16]
// ---------------------------------------------------------------------------
#define K3_WARPS 8
#define K3_NPW 4                              // nodes per warp
#define K3_NODES_BLK (K3_WARPS * K3_NPW)      // 32
#define K3_GRID ((NN + K3_NODES_BLK - 1) / K3_NODES_BLK)   // 313

#define SM3_WT 0
#define SM3_SU (SM3_WT + 32 * 64 * 16)                     // 32768
#define SM3_WO (SM3_SU + K3_WARPS * 8 * 32 * 16)           // +32768 = 65536
#define SM3_BT (SM3_WO + PP * 64 * 4)                      // +3072  = 68608
#define SM3_BO (SM3_BT + 64 * 4)                           // +256   = 68864
#define SM3_TOT (SM3_BO + 64)                              //        = 68928

__global__ void __launch_bounds__(K3_WARPS * 32, 2)
k_final(const float* __restrict__ W_tcn,
        const float* __restrict__ b_tcn,
        const float* __restrict__ W_out,
        const float* __restrict__ b_out,
        float* __restrict__ out) {
    extern __shared__ char dsm[];
    float4 (*sWt4)[64] = reinterpret_cast<float4(*)[64]>(dsm + SM3_WT);
    float4 (*su4)[8][32] = reinterpret_cast<float4(*)[8][32]>(dsm + SM3_SU);
    float*  sWoT = reinterpret_cast<float*>(dsm + SM3_WO);
    float*  sbt  = reinterpret_cast<float*>(dsm + SM3_BT);
    float*  sbo  = reinterpret_cast<float*>(dsm + SM3_BO);

    int tid = threadIdx.x;
    int nthr = K3_WARPS * 32;
    for (int idx = tid; idx < 32 * 64; idx += nthr) {
        int ip = idx >> 6, o = idx & 63;
        const float* wb = W_tcn + o * 192 + ip * 6;   // i = 2ip, taps 0,1
        sWt4[ip][o] = make_float4(wb[0], wb[1], wb[3], wb[4]);
    }
    for (int idx = tid; idx < PP * 64; idx += nthr) {
        int p = idx >> 6, o = idx & 63;
        sWoT[p * 64 + o] = W_out[o * PP + p];
    }
    if (tid < 64) sbt[tid] = b_tcn[tid];
    if (tid < PP) sbo[tid] = b_out[tid];
    __syncthreads();

    int w = tid >> 5, lane = tid & 31;
    int nBase = (blockIdx.x * K3_WARPS + w) * K3_NPW;

    // ---- load relu'd agg, scatter to interleaved su4 ----
    int tap = (lane >> 4) & 1;
    int hb8 = (lane & 15) * 8;
    #pragma unroll
    for (int m = 0; m < K3_NPW; m++) {
        int node = nBase + m;
        int nd = node < NN ? node : NN - 1;
        const float4* ar = reinterpret_cast<const float4*>(g_agg + (size_t)nd * ROWF);
        float4 r0 = __ldg(ar + lane);        // b = 0 data
        float4 r1 = __ldg(ar + lane + 32);   // b = 1 data
        float* d0 = reinterpret_cast<float*>(&su4[w][m * 2 + 0][0]);
        float* d1 = reinterpret_cast<float*>(&su4[w][m * 2 + 1][0]);
        // float f = 4*lane+jj: dst = 8*(lane&15) + 4*(jj>>1) + 2*(jj&1) + tap
        d0[hb8 + 0 + tap] = r0.x;  d0[hb8 + 2 + tap] = r0.y;
        d0[hb8 + 4 + tap] = r0.z;  d0[hb8 + 6 + tap] = r0.w;
        d1[hb8 + 0 + tap] = r1.x;  d1[hb8 + 2 + tap] = r1.y;
        d1[hb8 + 4 + tap] = r1.z;  d1[hb8 + 6 + tap] = r1.w;
    }
    __syncwarp();

    // ---- z-stage: 8 pairs, float4-packed weights ----
    float z0[8], z1[8];
    #pragma unroll
    for (int pp = 0; pp < 8; pp++) { z0[pp] = sbt[lane]; z1[pp] = sbt[lane + 32]; }
    #pragma unroll 4
    for (int ip = 0; ip < 32; ip++) {
        float4 wA = sWt4[ip][lane];
        float4 wB = sWt4[ip][lane + 32];
        #pragma unroll
        for (int pp = 0; pp < 8; pp++) {
            float4 u = su4[w][pp][ip];
            z0[pp] = fmaf(wA.x, u.x, fmaf(wA.y, u.y,
                     fmaf(wA.z, u.z, fmaf(wA.w, u.w, z0[pp]))));
            z1[pp] = fmaf(wB.x, u.x, fmaf(wB.y, u.y,
                     fmaf(wB.z, u.z, fmaf(wB.w, u.w, z1[pp]))));
        }
    }
    __syncwarp();
    #pragma unroll
    for (int pp = 0; pp < 8; pp++) {
        float* zf = reinterpret_cast<float*>(&su4[w][pp][0]);
        zf[lane]      = fmaxf(z0[pp], 0.0f);
        zf[lane + 32] = fmaxf(z1[pp], 0.0f);
    }
    __syncwarp();

    // ---- y-stage: 96 outputs (8 pairs x 12) in 3 exact lane-rounds ----
    #pragma unroll
    for (int r = 0; r < 3; r++) {
        int q = lane + r * 32;               // 0..95
        int pp = q / PP;
        int p  = q - pp * PP;
        float y = sbo[p];
        const float4* z4 = &su4[w][pp][0];
        const float4* w4 = reinterpret_cast<const float4*>(sWoT + p * 64);
        #pragma unroll 4
        for (int oc = 0; oc < 16; oc++) {
            float4 zz = z4[oc];
            float4 ww = w4[oc];
            y = fmaf(zz.x, ww.x, fmaf(zz.y, ww.y,
                fmaf(zz.z, ww.z, fmaf(zz.w, ww.w, y))));
        }
        int node = nBase + (pp >> 1);
        int b = pp & 1;
        if (node < NN)
            out[((size_t)b * PP + p) * NN + node] = y;
    }
}

// ---------------------------------------------------------------------------
extern "C" void kernel_launch(void* const* d_in, const int* in_sizes, int n_in,
                              void* d_out, int out_size) {
    const float* x     = (const float*)d_in[0];
    const int*   row   = (const int*)  d_in[1];
    const int*   col   = (const int*)  d_in[2];
    const float* vals  = (const float*)d_in[3];
    const float* W_in  = (const float*)d_in[4];
    const float* b_in  = (const float*)d_in[5];
    const float* W_tcn = (const float*)d_in[6];
    const float* b_tcn = (const float*)d_in[7];
    const float* W_out = (const float*)d_in[8];
    const float* b_out = (const float*)d_in[9];
    float* out = (float*)d_out;

    static bool attr_set = false;
    if (!attr_set) {
        cudaFuncSetAttribute(k_final,
                             cudaFuncAttributeMaxDynamicSharedMemorySize, SM3_TOT);
        attr_set = true;
    }

    k_proj_bin<<<1250, 256>>>(x, W_in, b_in, row, col, vals);
    k_gather<<<1250, 256>>>();
    k_final<<<K3_GRID, K3_WARPS * 32, SM3_TOT>>>(W_tcn, b_tcn, W_out, b_out, out);
}